// round 15
// baseline (speedup 1.0000x reference)
#include <cuda_runtime.h>
#include <cstdint>

#define D_MODEL 1024
#define NHEAD   16
#define DHEAD   64
#define DFF_SZ  4096
#define BATCH   2
#define SEQ     2048
#define MROWS   (BATCH*SEQ)   // 4096
#define MB      (1024*1024)

// ---------------- scratch (device globals; no allocations allowed) ----------
__device__ float g_q  [(size_t)MROWS * D_MODEL];
__device__ float g_ctx[(size_t)MROWS * D_MODEL];
__device__ float g_tmp[(size_t)MROWS * D_MODEL];
__device__ float g_x1 [(size_t)MROWS * D_MODEL];
__device__ float g_x2 [(size_t)MROWS * D_MODEL];
__device__ float g_ff [(size_t)MROWS * DFF_SZ];
__device__ float g_wc [(size_t)16 * MB];
__device__ float g_xq [(size_t)MROWS * D_MODEL];
__device__ float g_enct[(size_t)MROWS * D_MODEL];
__device__ float g_x1t[(size_t)MROWS * D_MODEL];
__device__ float g_x2t[(size_t)MROWS * D_MODEL];
__device__ float g_qkv[(size_t)MROWS * 3 * D_MODEL];   // fused self QKV (V part unused)
__device__ float g_kv [(size_t)MROWS * 2 * D_MODEL];   // fused cross KV (V part unused)
__device__ float g_vt [(size_t)BATCH * NHEAD * DHEAD * SEQ]; // V transposed [b,h,d,s]
__device__ float g_bqkv[3 * D_MODEL];
__device__ float g_bkv [2 * D_MODEL];

// ---------------- tf32 / mma helpers ----------------------------------------
__device__ __forceinline__ float to_tf32(float x) {
    uint32_t u;
    asm("cvt.rna.tf32.f32 %0, %1;" : "=r"(u) : "f"(x));
    return __uint_as_float(u);
}

__device__ __forceinline__ void mma_tf32(float d[4], const uint32_t a[4],
                                         const uint32_t b[2]) {
    asm volatile(
        "mma.sync.aligned.m16n8k8.row.col.f32.tf32.tf32.f32 "
        "{%0,%1,%2,%3}, {%4,%5,%6,%7}, {%8,%9}, {%0,%1,%2,%3};"
        : "+f"(d[0]), "+f"(d[1]), "+f"(d[2]), "+f"(d[3])
        : "r"(a[0]), "r"(a[1]), "r"(a[2]), "r"(a[3]), "r"(b[0]), "r"(b[1]));
}

__device__ __forceinline__ void ldsm_x4(uint32_t r[4], uint32_t addr) {
    asm volatile("ldmatrix.sync.aligned.m8n8.x4.shared.b16 {%0,%1,%2,%3}, [%4];"
                 : "=r"(r[0]), "=r"(r[1]), "=r"(r[2]), "=r"(r[3]) : "r"(addr));
}

__device__ __forceinline__ void cp_async16(uint32_t dst, const void* src) {
    asm volatile("cp.async.cg.shared.global [%0], [%1], 16;"
                 :: "r"(dst), "l"(src));
}
#define CP_ASYNC_COMMIT() asm volatile("cp.async.commit_group;" ::: "memory")
#define CP_ASYNC_WAIT(n)  asm volatile("cp.async.wait_group %0;" :: "n"(n) : "memory")

// ---------------- batched tf32 rounding / copy --------------------------------
#define NJOBS 17
struct CvtJobs {
    const float* src[NJOBS];
    float* dst[NJOBS];
    int n4[NJOBS];
    int rnd[NJOBS];
};

__global__ void __launch_bounds__(256) cvt_batch_kernel(CvtJobs j)
{
    const int job = blockIdx.y;
    const int n4 = j.n4[job];
    const int rnd = j.rnd[job];
    const float4* s = (const float4*)j.src[job];
    float4* d = (float4*)j.dst[job];
    for (int i = blockIdx.x * blockDim.x + threadIdx.x; i < n4;
         i += gridDim.x * blockDim.x) {
        float4 v = s[i];
        if (rnd)
            d[i] = make_float4(to_tf32(v.x), to_tf32(v.y), to_tf32(v.z), to_tf32(v.w));
        else
            d[i] = v;
    }
}

// ============================================================================
// TF32 tensor-core GEMM (R11 core): 128x128 CTA, 256 thr, 8 warps of 64x32,
// 3-stage cp.async pipeline, de-bursted prefetch, ldmatrix fragment loads.
// Optional transposed-V epilogue: columns >= vcol0 are written d-major into
// vt[b, h, d, s] instead of C (feeds attention PV ldmatrix B-frags).
// ============================================================================
#define ASTRIDE 36
#define STAGE_F (128 * ASTRIDE)
#define STAGE_B (2 * STAGE_F * 4)
#define GEMM_SMEM (3 * STAGE_B)          // 110592 bytes

__device__ __forceinline__ void gemm_body(
    const float* __restrict__ A, const float* __restrict__ W,
    const float* __restrict__ bias, float* __restrict__ C,
    int N, int K, int flags, int bm, int bn, float* smem,
    float* __restrict__ vt, int vcol0)
{
    const int t      = threadIdx.x;
    const int lane   = t & 31;
    const int wid    = t >> 5;
    const int warp_m = wid >> 2;
    const int warp_n = wid & 3;
    const int lr     = lane >> 2;
    const int lc     = lane & 3;

    const int row  = t >> 1;
    const int half = t & 1;
    const float* gA = A + (size_t)(bm * 128 + row) * K + half * 16;
    const float* gW = W + (size_t)(bn * 128 + row) * K + half * 16;
    const uint32_t sbase = (uint32_t)__cvta_generic_to_shared(smem);
    const uint32_t cpoff = (row * ASTRIDE + half * 16) * 4;

    const int g8 = lane >> 3, r8 = lane & 7;
    uint32_t aoff[4], boff[2];
#pragma unroll
    for (int mt = 0; mt < 4; mt++) {
        int rr = warp_m * 64 + mt * 16 + (g8 & 1) * 8 + r8;
        int cc = (g8 >> 1) * 4;
        aoff[mt] = (rr * ASTRIDE + cc) * 4;
    }
#pragma unroll
    for (int p = 0; p < 2; p++) {
        int rr = warp_n * 32 + p * 16 + (g8 >> 1) * 8 + r8;
        int cc = (g8 & 1) * 4;
        boff[p] = (rr * ASTRIDE + cc) * 4;
    }

    float acc[4][4][4];
#pragma unroll
    for (int m = 0; m < 4; m++)
#pragma unroll
        for (int n = 0; n < 4; n++)
#pragma unroll
            for (int e = 0; e < 4; e++) acc[m][n][e] = 0.f;

    const int nchunk = K >> 5;

#pragma unroll
    for (int pc = 0; pc < 2; pc++) {
        const uint32_t sa = sbase + pc * STAGE_B + cpoff;
        const uint32_t sb = sa + STAGE_F * 4;
        const float* ga = gA + pc * 32;
        const float* gw = gW + pc * 32;
#pragma unroll
        for (int i = 0; i < 4; i++) {
            cp_async16(sa + i * 16, ga + i * 4);
            cp_async16(sb + i * 16, gw + i * 4);
        }
        CP_ASYNC_COMMIT();
    }

    int st = 0;
    for (int c = 0; c < nchunk; c++) {
        if (c + 1 < nchunk) { CP_ASYNC_WAIT(1); } else { CP_ASYNC_WAIT(0); }
        __syncthreads();

        const bool pf = (c + 2 < nchunk);
        int is = st + 2; if (is >= 3) is -= 3;
        const uint32_t psa = sbase + is * STAGE_B + cpoff;
        const uint32_t psb = psa + STAGE_F * 4;
        const float* pga = gA + (c + 2) * 32;
        const float* pgw = gW + (c + 2) * 32;

        const uint32_t abase = sbase + st * STAGE_B;
        const uint32_t bbase = abase + STAGE_F * 4;
#pragma unroll
        for (int s = 0; s < 4; s++) {
            uint32_t af[4][4], bp[2][4];
#pragma unroll
            for (int mt = 0; mt < 4; mt++)
                ldsm_x4(af[mt], abase + aoff[mt] + s * 32);
#pragma unroll
            for (int p = 0; p < 2; p++)
                ldsm_x4(bp[p], bbase + boff[p] + s * 32);
#pragma unroll
            for (int mt = 0; mt < 4; mt++)
#pragma unroll
                for (int nt = 0; nt < 4; nt++)
                    mma_tf32(acc[mt][nt], af[mt], &bp[nt >> 1][(nt & 1) * 2]);
            if (pf) {
                cp_async16(psa + s * 16, pga + s * 4);
                cp_async16(psb + s * 16, pgw + s * 4);
            }
        }
        if (pf) CP_ASYNC_COMMIT();
        st = (st + 1 == 3) ? 0 : st + 1;
    }

    const int relu = flags & 1;
    const int rnd  = flags & 2;
    const int r0  = bm * 128 + warp_m * 64;
    const int c0g = bn * 128 + warp_n * 32;

    if (vt != nullptr && bn * 128 >= vcol0) {
        // transposed V epilogue: vt[b, h, d, s]
        const int bb = (bm * 128) >> 11;         // batch of this tile (no crossing)
        float* vtb = vt + (size_t)bb * NHEAD * DHEAD * SEQ;
#pragma unroll
        for (int n = 0; n < 4; n++) {
            const int colr = c0g + n * 8 + 2 * lc - vcol0;
            const int hd0 = colr;                 // h*64 + d
            float2 bv = *(const float2*)(bias + c0g + n * 8 + 2 * lc);
#pragma unroll
            for (int m = 0; m < 4; m++) {
                const int s = (r0 + m * 16 + lr) & (SEQ - 1);
                float v00 = acc[m][n][0] + bv.x;
                float v01 = acc[m][n][1] + bv.y;
                float v10 = acc[m][n][2] + bv.x;
                float v11 = acc[m][n][3] + bv.y;
                if (rnd) {
                    v00 = to_tf32(v00); v01 = to_tf32(v01);
                    v10 = to_tf32(v10); v11 = to_tf32(v11);
                }
                float* p0 = vtb + (size_t)hd0 * SEQ + s;
                float* p1 = vtb + (size_t)(hd0 + 1) * SEQ + s;
                p0[0] = v00; p1[0] = v01;
                p0[8] = v10; p1[8] = v11;
            }
        }
        return;
    }

#pragma unroll
    for (int n = 0; n < 4; n++) {
        const int col = c0g + n * 8 + 2 * lc;
        float2 bv = *(const float2*)(bias + col);
#pragma unroll
        for (int m = 0; m < 4; m++) {
            const int r = r0 + m * 16 + lr;
            float2 v0 = make_float2(acc[m][n][0] + bv.x, acc[m][n][1] + bv.y);
            float2 v1 = make_float2(acc[m][n][2] + bv.x, acc[m][n][3] + bv.y);
            if (relu) {
                v0.x = fmaxf(v0.x, 0.f); v0.y = fmaxf(v0.y, 0.f);
                v1.x = fmaxf(v1.x, 0.f); v1.y = fmaxf(v1.y, 0.f);
            }
            if (rnd) {
                v0.x = to_tf32(v0.x); v0.y = to_tf32(v0.y);
                v1.x = to_tf32(v1.x); v1.y = to_tf32(v1.y);
            }
            *(float2*)(C + (size_t)r * N + col)       = v0;
            *(float2*)(C + (size_t)(r + 8) * N + col) = v1;
        }
    }
}

__global__ void __launch_bounds__(256, 2) gemm_tc(
    const float* __restrict__ A, const float* __restrict__ W,
    const float* __restrict__ bias, float* __restrict__ C,
    int M, int N, int K, int flags, float* vt, int vcol0)
{
    extern __shared__ float smem[];
    gemm_body(A, W, bias, C, N, K, flags, blockIdx.y, blockIdx.x, smem, vt, vcol0);
}

// Two independent GEMMs (same M, K) in one launch; GEMM2 may route V cols to vt.
__global__ void __launch_bounds__(256, 2) gemm_tc_dual(
    const float* __restrict__ A1, const float* __restrict__ W1,
    const float* __restrict__ b1, float* __restrict__ C1, int N1,
    const float* __restrict__ A2, const float* __restrict__ W2,
    const float* __restrict__ b2, float* __restrict__ C2, int N2,
    int K, float* vt2, int vcol02)
{
    extern __shared__ float smem[];
    const int split = N1 >> 7;
    if ((int)blockIdx.x < split)
        gemm_body(A1, W1, b1, C1, N1, K, 2, blockIdx.y, blockIdx.x, smem,
                  nullptr, 0);
    else
        gemm_body(A2, W2, b2, C2, N2, K, 2, blockIdx.y, blockIdx.x - split, smem,
                  vt2, vcol02);
}

// ============================================================================
// Tensor-core flash attention: 128x64 tiles, 8 warps, K/V depth-2 cp.async.
// K from kv-major buffer (S-phase ldmatrix B-frags); V from d-major vt buffer
// (PV-phase ldmatrix B-frags, same pattern). P A-frags via ldmatrix.
// ============================================================================
#define KP 68
#define VP 68
#define PP 76
#define ATTN_SMEM ((2*64*KP + 2*64*VP + 128*PP) * 4)   // 108544 bytes

__global__ void __launch_bounds__(256, 2) attn_tc(
    const float* __restrict__ Q, const float* __restrict__ K,
    const float* __restrict__ VT, const int* __restrict__ mask,
    float* __restrict__ O, int Skv, int causal, int qs, int ks)
{
    extern __shared__ float sm[];
    float* p_s = sm + 2 * 64 * KP + 2 * 64 * VP; // [128][PP]

    const int t    = threadIdx.x;
    const int lane = t & 31;
    const int wid  = t >> 5;
    const int lr   = lane >> 2;
    const int lc   = lane & 3;
    const int wr0  = wid * 16;
    const int qt   = causal ? (gridDim.x - 1 - blockIdx.x) : blockIdx.x;
    const int h    = blockIdx.y;
    const int b    = blockIdx.z;
    const int qrow0 = qt * 128;

    const size_t qbase  = ((size_t)(b * SEQ + qrow0)) * qs + h * DHEAD;
    const size_t obase  = ((size_t)(b * SEQ + qrow0)) * D_MODEL + h * DHEAD;
    const size_t vtbase = ((size_t)(b * NHEAD + h)) * DHEAD * Skv;
    const uint32_t smadr = (uint32_t)__cvta_generic_to_shared(sm);
    const uint32_t kadr  = smadr;
    const uint32_t vadr  = smadr + 2 * 64 * KP * 4;
    const uint32_t padr  = smadr + (2 * 64 * KP + 2 * 64 * VP) * 4;

    const int g8 = lane >> 3, r8 = lane & 7;
    uint32_t kboff[4], vboff[4];
#pragma unroll
    for (int p = 0; p < 4; p++) {
        int rr = p * 16 + (g8 >> 1) * 8 + r8;
        int cc = (g8 & 1) * 4;
        kboff[p] = (rr * KP + cc) * 4;
        vboff[p] = (rr * VP + cc) * 4;
    }
    const uint32_t paoff = ((wr0 + (g8 & 1) * 8 + r8) * PP + (g8 >> 1) * 4) * 4;

    const int ntiles = causal ? (2 * qt + 2) : (Skv >> 6);

    // ---- prologue: issue K/V tiles 0,1 ----
#pragma unroll
    for (int pt = 0; pt < 2; pt++) {
        if (pt < ntiles) {
            const size_t kb = ((size_t)(b * Skv + pt * 64)) * ks + h * DHEAD;
            const uint32_t ka = kadr + pt * 64 * KP * 4;
            const uint32_t va = vadr + pt * 64 * VP * 4;
#pragma unroll
            for (int e = 0; e < 4; e++) {
                int f4 = e * 256 + t;
                int r = f4 >> 4, c4 = f4 & 15;
                cp_async16(ka + (r * KP + c4 * 4) * 4,
                           K + kb + (size_t)r * ks + c4 * 4);
                cp_async16(va + (r * VP + c4 * 4) * 4,
                           VT + vtbase + (size_t)r * Skv + pt * 64 + c4 * 4);
            }
            CP_ASYNC_COMMIT();
        }
    }

    // ---- stage Q (scale by 1/8; pre-rounded tf32, scale exact) ----
#pragma unroll
    for (int e = 0; e < 8; e++) {
        int f4 = e * 256 + t;
        int r = f4 >> 4, c4 = f4 & 15;
        float4 qv = *(const float4*)(Q + qbase + (size_t)r * qs + c4 * 4);
        float* dst = p_s + r * PP + c4 * 4;
        dst[0] = qv.x * 0.125f;
        dst[1] = qv.y * 0.125f;
        dst[2] = qv.z * 0.125f;
        dst[3] = qv.w * 0.125f;
    }
    __syncthreads();
    uint32_t qa[8][4];
#pragma unroll
    for (int kf = 0; kf < 8; kf++)
        ldsm_x4(qa[kf], padr + paoff + kf * 32);

    float m_i[2] = {-1e30f, -1e30f};
    float l_i[2] = {0.f, 0.f};
    float oacc[8][4];
#pragma unroll
    for (int nf = 0; nf < 8; nf++)
#pragma unroll
        for (int e = 0; e < 4; e++) oacc[nf][e] = 0.f;

    const int r0g = qrow0 + wr0 + lr;

    for (int jt = 0; jt < ntiles; jt++) {
        if (jt + 1 < ntiles) { CP_ASYNC_WAIT(1); } else { CP_ASYNC_WAIT(0); }
        __syncthreads();

        const uint32_t kst = kadr + (jt & 1) * 64 * KP * 4;
        const uint32_t vst = vadr + (jt & 1) * 64 * VP * 4;

        // ---- S = Q K^T (ldmatrix B-frags) ----
        float sacc[8][4];
#pragma unroll
        for (int nf = 0; nf < 8; nf++)
#pragma unroll
            for (int e = 0; e < 4; e++) sacc[nf][e] = 0.f;

#pragma unroll
        for (int kk = 0; kk < 8; kk++) {
            uint32_t bp[4][4];
#pragma unroll
            for (int p = 0; p < 4; p++)
                ldsm_x4(bp[p], kst + kboff[p] + kk * 32);
#pragma unroll
            for (int nf = 0; nf < 8; nf++)
                mma_tf32(sacc[nf], qa[kk], &bp[nf >> 1][(nf & 1) * 2]);
        }

        if (causal) {
            if (jt >= 2 * qt) {
#pragma unroll
                for (int nf = 0; nf < 8; nf++) {
                    int c0 = jt * 64 + nf * 8 + 2 * lc;
                    if (c0     > r0g)     sacc[nf][0] = -1e9f;
                    if (c0 + 1 > r0g)     sacc[nf][1] = -1e9f;
                    if (c0     > r0g + 8) sacc[nf][2] = -1e9f;
                    if (c0 + 1 > r0g + 8) sacc[nf][3] = -1e9f;
                }
            }
        } else {
            const int* mrow0 = mask + ((size_t)b * SEQ + r0g) * Skv + jt * 64;
            const int* mrow1 = mrow0 + 8 * Skv;
#pragma unroll
            for (int nf = 0; nf < 8; nf++) {
                int2 m0 = *(const int2*)(mrow0 + nf * 8 + 2 * lc);
                int2 m1 = *(const int2*)(mrow1 + nf * 8 + 2 * lc);
                if (!m0.x) sacc[nf][0] = -1e9f;
                if (!m0.y) sacc[nf][1] = -1e9f;
                if (!m1.x) sacc[nf][2] = -1e9f;
                if (!m1.y) sacc[nf][3] = -1e9f;
            }
        }

        // ---- online softmax (raw-fp32 P store; HW truncates operand) ----
        float mx0 = -1e30f, mx1 = -1e30f;
#pragma unroll
        for (int nf = 0; nf < 8; nf++) {
            mx0 = fmaxf(mx0, fmaxf(sacc[nf][0], sacc[nf][1]));
            mx1 = fmaxf(mx1, fmaxf(sacc[nf][2], sacc[nf][3]));
        }
        mx0 = fmaxf(mx0, __shfl_xor_sync(0xffffffffu, mx0, 1));
        mx0 = fmaxf(mx0, __shfl_xor_sync(0xffffffffu, mx0, 2));
        mx1 = fmaxf(mx1, __shfl_xor_sync(0xffffffffu, mx1, 1));
        mx1 = fmaxf(mx1, __shfl_xor_sync(0xffffffffu, mx1, 2));
        float newm0 = fmaxf(m_i[0], mx0);
        float newm1 = fmaxf(m_i[1], mx1);
        float a0 = __expf(m_i[0] - newm0);
        float a1 = __expf(m_i[1] - newm1);
        m_i[0] = newm0; m_i[1] = newm1;

        float rs0 = 0.f, rs1 = 0.f;
#pragma unroll
        for (int nf = 0; nf < 8; nf++) {
            float p0 = __expf(sacc[nf][0] - newm0);
            float p1 = __expf(sacc[nf][1] - newm0);
            float p2 = __expf(sacc[nf][2] - newm1);
            float p3 = __expf(sacc[nf][3] - newm1);
            rs0 += p0 + p1;
            rs1 += p2 + p3;
            float* pr0 = p_s + (wr0 + lr) * PP + nf * 8 + 2 * lc;
            *(float2*)pr0            = make_float2(p0, p1);
            *(float2*)(pr0 + 8 * PP) = make_float2(p2, p3);
            oacc[nf][0] *= a0; oacc[nf][1] *= a0;
            oacc[nf][2] *= a1; oacc[nf][3] *= a1;
        }
        rs0 += __shfl_xor_sync(0xffffffffu, rs0, 1);
        rs0 += __shfl_xor_sync(0xffffffffu, rs0, 2);
        rs1 += __shfl_xor_sync(0xffffffffu, rs1, 1);
        rs1 += __shfl_xor_sync(0xffffffffu, rs1, 2);
        l_i[0] = l_i[0] * a0 + rs0;
        l_i[1] = l_i[1] * a1 + rs1;
        __syncwarp();   // p_s rows are warp-private

        // ---- O += P V (ldmatrix P A-frags + ldmatrix V^T B-frags) ----
#pragma unroll
        for (int kk = 0; kk < 8; kk++) {
            uint32_t af[4];
            ldsm_x4(af, padr + paoff + kk * 32);
            uint32_t bp[4][4];
#pragma unroll
            for (int p = 0; p < 4; p++)
                ldsm_x4(bp[p], vst + vboff[p] + kk * 32);
#pragma unroll
            for (int nf = 0; nf < 8; nf++)
                mma_tf32(oacc[nf], af, &bp[nf >> 1][(nf & 1) * 2]);
        }

        __syncthreads();   // all warps done reading stage (jt&1) before refill
        if (jt + 2 < ntiles) {
            const int s = jt & 1;
            const size_t kb = ((size_t)(b * Skv + (jt + 2) * 64)) * ks + h * DHEAD;
            const uint32_t ka = kadr + s * 64 * KP * 4;
            const uint32_t va = vadr + s * 64 * VP * 4;
#pragma unroll
            for (int e = 0; e < 4; e++) {
                int f4 = e * 256 + t;
                int r = f4 >> 4, c4 = f4 & 15;
                cp_async16(ka + (r * KP + c4 * 4) * 4,
                           K + kb + (size_t)r * ks + c4 * 4);
                cp_async16(va + (r * VP + c4 * 4) * 4,
                           VT + vtbase + (size_t)r * Skv + (jt + 2) * 64 + c4 * 4);
            }
            CP_ASYNC_COMMIT();
        }
    }

    // store tf32-rounded ctx (feeds O-projection GEMM)
    float inv0 = 1.f / l_i[0];
    float inv1 = 1.f / l_i[1];
#pragma unroll
    for (int nf = 0; nf < 8; nf++) {
        float* o0 = O + obase + (size_t)(wr0 + lr) * D_MODEL + nf * 8 + 2 * lc;
        float* o1 = o0 + 8 * D_MODEL;
        *(float2*)o0 = make_float2(to_tf32(oacc[nf][0] * inv0),
                                   to_tf32(oacc[nf][1] * inv0));
        *(float2*)o1 = make_float2(to_tf32(oacc[nf][2] * inv1),
                                   to_tf32(oacc[nf][3] * inv1));
    }
}

// ---------------- fused residual add + LayerNorm: warp-per-row --------------
__global__ void __launch_bounds__(256) add_ln_kernel(
    const float* __restrict__ a, const float* __restrict__ r,
    const float* __restrict__ g, const float* __restrict__ be,
    float* __restrict__ out, float* __restrict__ out_t)
{
    const int row  = (blockIdx.x * blockDim.x + threadIdx.x) >> 5;
    const int lane = threadIdx.x & 31;
    const size_t base = (size_t)row * D_MODEL;

    float v[32];
    float s = 0.f, q = 0.f;
#pragma unroll
    for (int i = 0; i < 8; i++) {
        const int col = lane * 4 + i * 128;
        float4 va = *(const float4*)(a + base + col);
        float4 vr = *(const float4*)(r + base + col);
        float v0 = va.x + vr.x, v1 = va.y + vr.y;
        float v2 = va.z + vr.z, v3 = va.w + vr.w;
        v[i * 4 + 0] = v0; v[i * 4 + 1] = v1; v[i * 4 + 2] = v2; v[i * 4 + 3] = v3;
        s += v0 + v1 + v2 + v3;
        q += v0 * v0 + v1 * v1 + v2 * v2 + v3 * v3;
    }
#pragma unroll
    for (int off = 16; off >= 1; off >>= 1) {
        s += __shfl_xor_sync(0xffffffffu, s, off);
        q += __shfl_xor_sync(0xffffffffu, q, off);
    }
    float mu  = s * (1.f / D_MODEL);
    float var = q * (1.f / D_MODEL) - mu * mu;
    float rstd = rsqrtf(var + 1e-5f);

#pragma unroll
    for (int i = 0; i < 8; i++) {
        const int col = lane * 4 + i * 128;
        float4 vg = *(const float4*)(g + col);
        float4 vb = *(const float4*)(be + col);
        float4 o;
        o.x = (v[i * 4 + 0] - mu) * rstd * vg.x + vb.x;
        o.y = (v[i * 4 + 1] - mu) * rstd * vg.y + vb.y;
        o.z = (v[i * 4 + 2] - mu) * rstd * vg.z + vb.z;
        o.w = (v[i * 4 + 3] - mu) * rstd * vg.w + vb.w;
        *(float4*)(out + base + col) = o;
        if (out_t)
            *(float4*)(out_t + base + col) =
                make_float4(to_tf32(o.x), to_tf32(o.y), to_tf32(o.z), to_tf32(o.w));
    }
}

// ---------------- launch ----------------------------------------------------
static void run_gemm(const float* A, const float* W, const float* b, float* C,
                     int M, int N, int K, int flags,
                     float* vt = nullptr, int vcol0 = 0)
{
    dim3 grid(N / 128, M / 128);
    gemm_tc<<<grid, 256, GEMM_SMEM>>>(A, W, b, C, M, N, K, flags, vt, vcol0);
}

extern "C" void kernel_launch(void* const* d_in, const int* in_sizes, int n_in,
                              void* d_out, int out_size)
{
    (void)in_sizes; (void)n_in; (void)out_size;
    const float* x    = (const float*)d_in[0];
    const float* enc  = (const float*)d_in[1];
    const int* src_mask = (const int*)d_in[2];
    const int* tgt_mask = (const int*)d_in[3];
    const float* sa_Wq = (const float*)d_in[4];
    const float* sa_bq = (const float*)d_in[5];
    const float* sa_Wk = (const float*)d_in[6];
    const float* sa_bk = (const float*)d_in[7];
    const float* sa_Wv = (const float*)d_in[8];
    const float* sa_bv = (const float*)d_in[9];
    const float* sa_Wo = (const float*)d_in[10];
    const float* sa_bo = (const float*)d_in[11];
    const float* ca_Wq = (const float*)d_in[12];
    const float* ca_bq = (const float*)d_in[13];
    const float* ca_Wk = (const float*)d_in[14];
    const float* ca_bk = (const float*)d_in[15];
    const float* ca_Wv = (const float*)d_in[16];
    const float* ca_bv = (const float*)d_in[17];
    const float* ca_Wo = (const float*)d_in[18];
    const float* ca_bo = (const float*)d_in[19];
    const float* ff_W1 = (const float*)d_in[20];
    const float* ff_b1 = (const float*)d_in[21];
    const float* ff_W2 = (const float*)d_in[22];
    const float* ff_b2 = (const float*)d_in[23];
    const float* ln1_g = (const float*)d_in[24];
    const float* ln1_b = (const float*)d_in[25];
    const float* ln2_g = (const float*)d_in[26];
    const float* ln2_b = (const float*)d_in[27];
    const float* ln3_g = (const float*)d_in[28];
    const float* ln3_b = (const float*)d_in[29];
    float* out = (float*)d_out;

    float *q, *ctx, *tmp, *x1, *x2, *ff;
    float *wc, *xq, *enct, *x1t, *x2t, *qkv, *kv, *vt, *bqkv, *bkv;
    cudaGetSymbolAddress((void**)&q,    g_q);
    cudaGetSymbolAddress((void**)&ctx,  g_ctx);
    cudaGetSymbolAddress((void**)&tmp,  g_tmp);
    cudaGetSymbolAddress((void**)&x1,   g_x1);
    cudaGetSymbolAddress((void**)&x2,   g_x2);
    cudaGetSymbolAddress((void**)&ff,   g_ff);
    cudaGetSymbolAddress((void**)&wc,   g_wc);
    cudaGetSymbolAddress((void**)&xq,   g_xq);
    cudaGetSymbolAddress((void**)&enct, g_enct);
    cudaGetSymbolAddress((void**)&x1t,  g_x1t);
    cudaGetSymbolAddress((void**)&x2t,  g_x2t);
    cudaGetSymbolAddress((void**)&qkv,  g_qkv);
    cudaGetSymbolAddress((void**)&kv,   g_kv);
    cudaGetSymbolAddress((void**)&vt,   g_vt);
    cudaGetSymbolAddress((void**)&bqkv, g_bqkv);
    cudaGetSymbolAddress((void**)&bkv,  g_bkv);

    cudaFuncSetAttribute(gemm_tc, cudaFuncAttributeMaxDynamicSharedMemorySize,
                         GEMM_SMEM);
    cudaFuncSetAttribute(gemm_tc_dual, cudaFuncAttributeMaxDynamicSharedMemorySize,
                         GEMM_SMEM);
    cudaFuncSetAttribute(attn_tc, cudaFuncAttributeMaxDynamicSharedMemorySize,
                         ATTN_SMEM);

    float* wSAQ = wc + 0 * MB;  // wSAK, wSAV contiguous after -> fused QKV W
    float* wSAO = wc + 3 * MB;
    float* wCAQ = wc + 4 * MB;
    float* wCAK = wc + 5 * MB;  // wCAV contiguous after -> fused KV W
    float* wCAO = wc + 7 * MB;
    float* wFF1 = wc + 8 * MB;  float* wFF2 = wc + 12 * MB;

    CvtJobs jobs;
    const float* srcs[NJOBS] = {sa_Wq, sa_Wk, sa_Wv, sa_Wo, ca_Wq, ca_Wk, ca_Wv,
                                ca_Wo, ff_W1, ff_W2, x, enc,
                                sa_bq, sa_bk, sa_bv, ca_bk, ca_bv};
    float* dsts[NJOBS] = {wc, wc + MB, wc + 2 * MB, wSAO, wCAQ, wCAK, wc + 6 * MB,
                          wCAO, wFF1, wFF2, xq, enct,
                          bqkv, bqkv + D_MODEL, bqkv + 2 * D_MODEL,
                          bkv, bkv + D_MODEL};
    int n4s[NJOBS] = {MB/4, MB/4, MB/4, MB/4, MB/4, MB/4, MB/4, MB/4,
                      MB, MB, MB, MB, 256, 256, 256, 256, 256};
    int rnds[NJOBS] = {1,1,1,1,1,1,1,1,1,1,1,1, 0,0,0,0,0};
    for (int i = 0; i < NJOBS; i++) {
        jobs.src[i] = srcs[i]; jobs.dst[i] = dsts[i];
        jobs.n4[i] = n4s[i];   jobs.rnd[i] = rnds[i];
    }
    cvt_batch_kernel<<<dim3(1024, NJOBS), 256>>>(jobs);

    dim3 agrid(SEQ / 128, NHEAD, BATCH);
    const int LN_BLOCKS = MROWS / 8;

    // ---- self-attention (fused QKV projection; V columns routed to vt) ----
    run_gemm(xq, wSAQ, bqkv, qkv, MROWS, 3 * D_MODEL, D_MODEL, 2,
             vt, 2 * D_MODEL);
    attn_tc<<<agrid, 256, ATTN_SMEM>>>(qkv, qkv + D_MODEL, vt,
                                       tgt_mask, ctx, SEQ, 1,
                                       3 * D_MODEL, 3 * D_MODEL);
    run_gemm(ctx, wSAO, sa_bo, tmp, MROWS, D_MODEL, D_MODEL, 0);
    add_ln_kernel<<<LN_BLOCKS, 256>>>(x, tmp, ln1_g, ln1_b, x1, x1t);

    // ---- cross-attention: Q-proj and KV-proj fused; V columns to vt ----
    {
        dim3 grid((D_MODEL + 2 * D_MODEL) / 128, MROWS / 128);
        gemm_tc_dual<<<grid, 256, GEMM_SMEM>>>(
            x1t,  wCAQ, ca_bq, q,  D_MODEL,
            enct, wCAK, bkv,   kv, 2 * D_MODEL,
            D_MODEL, vt, D_MODEL);
    }
    attn_tc<<<agrid, 256, ATTN_SMEM>>>(q, kv, vt,
                                       src_mask, ctx, SEQ, 0,
                                       D_MODEL, 2 * D_MODEL);
    run_gemm(ctx, wCAO, ca_bo, tmp, MROWS, D_MODEL, D_MODEL, 0);
    add_ln_kernel<<<LN_BLOCKS, 256>>>(x1, tmp, ln2_g, ln2_b, x2, x2t);

    // ---- feed-forward ----
    run_gemm(x2t, wFF1, ff_b1, ff, MROWS, DFF_SZ, D_MODEL, 1 | 2);
    run_gemm(ff,  wFF2, ff_b2, tmp, MROWS, D_MODEL, DFF_SZ, 0);
    add_ln_kernel<<<LN_BLOCKS, 256>>>(x2, tmp, ln3_g, ln3_b, out, nullptr);
}

// round 16
// speedup vs baseline: 1.0198x; 1.0198x over previous
#include <cuda_runtime.h>
#include <cstdint>

#define D_MODEL 1024
#define NHEAD   16
#define DHEAD   64
#define DFF_SZ  4096
#define BATCH   2
#define SEQ     2048
#define MROWS   (BATCH*SEQ)   // 4096
#define MB      (1024*1024)

// ---------------- scratch (device globals; no allocations allowed) ----------
__device__ float g_q  [(size_t)MROWS * D_MODEL];
__device__ float g_ctx[(size_t)MROWS * D_MODEL];
__device__ float g_tmp[(size_t)MROWS * D_MODEL];
__device__ float g_x1 [(size_t)MROWS * D_MODEL];
__device__ float g_x2 [(size_t)MROWS * D_MODEL];
__device__ float g_ff [(size_t)MROWS * DFF_SZ];
__device__ float g_wc [(size_t)16 * MB];
__device__ float g_xq [(size_t)MROWS * D_MODEL];
__device__ float g_enct[(size_t)MROWS * D_MODEL];
__device__ float g_x1t[(size_t)MROWS * D_MODEL];
__device__ float g_x2t[(size_t)MROWS * D_MODEL];
__device__ float g_qkv[(size_t)MROWS * 3 * D_MODEL];   // fused self QKV (V cols -> vtA)
__device__ float g_kv [(size_t)MROWS * 2 * D_MODEL];   // fused cross KV (V cols -> vtB)
__device__ float g_vtA[(size_t)BATCH * NHEAD * DHEAD * SEQ]; // self V^T [b,h,d,s]
__device__ float g_vtB[(size_t)BATCH * NHEAD * DHEAD * SEQ]; // cross V^T [b,h,d,s]
__device__ float g_bqkv[3 * D_MODEL];
__device__ float g_bkv [2 * D_MODEL];

// ---------------- tf32 / mma helpers ----------------------------------------
__device__ __forceinline__ float to_tf32(float x) {
    uint32_t u;
    asm("cvt.rna.tf32.f32 %0, %1;" : "=r"(u) : "f"(x));
    return __uint_as_float(u);
}

__device__ __forceinline__ void mma_tf32(float d[4], const uint32_t a[4],
                                         const uint32_t b[2]) {
    asm volatile(
        "mma.sync.aligned.m16n8k8.row.col.f32.tf32.tf32.f32 "
        "{%0,%1,%2,%3}, {%4,%5,%6,%7}, {%8,%9}, {%0,%1,%2,%3};"
        : "+f"(d[0]), "+f"(d[1]), "+f"(d[2]), "+f"(d[3])
        : "r"(a[0]), "r"(a[1]), "r"(a[2]), "r"(a[3]), "r"(b[0]), "r"(b[1]));
}

__device__ __forceinline__ void ldsm_x4(uint32_t r[4], uint32_t addr) {
    asm volatile("ldmatrix.sync.aligned.m8n8.x4.shared.b16 {%0,%1,%2,%3}, [%4];"
                 : "=r"(r[0]), "=r"(r[1]), "=r"(r[2]), "=r"(r[3]) : "r"(addr));
}

__device__ __forceinline__ void cp_async16(uint32_t dst, const void* src) {
    asm volatile("cp.async.cg.shared.global [%0], [%1], 16;"
                 :: "r"(dst), "l"(src));
}
#define CP_ASYNC_COMMIT() asm volatile("cp.async.commit_group;" ::: "memory")
#define CP_ASYNC_WAIT(n)  asm volatile("cp.async.wait_group %0;" :: "n"(n) : "memory")

// ---------------- batched tf32 rounding / copy --------------------------------
#define NJOBS 17
struct CvtJobs {
    const float* src[NJOBS];
    float* dst[NJOBS];
    int n4[NJOBS];
    int rnd[NJOBS];
};

__global__ void __launch_bounds__(256) cvt_batch_kernel(CvtJobs j)
{
    const int job = blockIdx.y;
    const int n4 = j.n4[job];
    const int rnd = j.rnd[job];
    const float4* s = (const float4*)j.src[job];
    float4* d = (float4*)j.dst[job];
    for (int i = blockIdx.x * blockDim.x + threadIdx.x; i < n4;
         i += gridDim.x * blockDim.x) {
        float4 v = s[i];
        if (rnd)
            d[i] = make_float4(to_tf32(v.x), to_tf32(v.y), to_tf32(v.z), to_tf32(v.w));
        else
            d[i] = v;
    }
}

// ============================================================================
// TF32 tensor-core GEMM (R11 core): 128x128 CTA, 256 thr, 8 warps of 64x32,
// 3-stage cp.async pipeline, de-bursted prefetch, ldmatrix fragment loads.
// Optional transposed-V epilogue: columns >= vcol0 are written d-major into
// vt[b, h, d, s] instead of C (feeds attention PV ldmatrix B-frags).
// ============================================================================
#define ASTRIDE 36
#define STAGE_F (128 * ASTRIDE)
#define STAGE_B (2 * STAGE_F * 4)
#define GEMM_SMEM (3 * STAGE_B)          // 110592 bytes

__device__ __forceinline__ void gemm_body(
    const float* __restrict__ A, const float* __restrict__ W,
    const float* __restrict__ bias, float* __restrict__ C,
    int N, int K, int flags, int bm, int bn, float* smem,
    float* __restrict__ vt, int vcol0)
{
    const int t      = threadIdx.x;
    const int lane   = t & 31;
    const int wid    = t >> 5;
    const int warp_m = wid >> 2;
    const int warp_n = wid & 3;
    const int lr     = lane >> 2;
    const int lc     = lane & 3;

    const int row  = t >> 1;
    const int half = t & 1;
    const float* gA = A + (size_t)(bm * 128 + row) * K + half * 16;
    const float* gW = W + (size_t)(bn * 128 + row) * K + half * 16;
    const uint32_t sbase = (uint32_t)__cvta_generic_to_shared(smem);
    const uint32_t cpoff = (row * ASTRIDE + half * 16) * 4;

    const int g8 = lane >> 3, r8 = lane & 7;
    uint32_t aoff[4], boff[2];
#pragma unroll
    for (int mt = 0; mt < 4; mt++) {
        int rr = warp_m * 64 + mt * 16 + (g8 & 1) * 8 + r8;
        int cc = (g8 >> 1) * 4;
        aoff[mt] = (rr * ASTRIDE + cc) * 4;
    }
#pragma unroll
    for (int p = 0; p < 2; p++) {
        int rr = warp_n * 32 + p * 16 + (g8 >> 1) * 8 + r8;
        int cc = (g8 & 1) * 4;
        boff[p] = (rr * ASTRIDE + cc) * 4;
    }

    float acc[4][4][4];
#pragma unroll
    for (int m = 0; m < 4; m++)
#pragma unroll
        for (int n = 0; n < 4; n++)
#pragma unroll
            for (int e = 0; e < 4; e++) acc[m][n][e] = 0.f;

    const int nchunk = K >> 5;

#pragma unroll
    for (int pc = 0; pc < 2; pc++) {
        const uint32_t sa = sbase + pc * STAGE_B + cpoff;
        const uint32_t sb = sa + STAGE_F * 4;
        const float* ga = gA + pc * 32;
        const float* gw = gW + pc * 32;
#pragma unroll
        for (int i = 0; i < 4; i++) {
            cp_async16(sa + i * 16, ga + i * 4);
            cp_async16(sb + i * 16, gw + i * 4);
        }
        CP_ASYNC_COMMIT();
    }

    int st = 0;
    for (int c = 0; c < nchunk; c++) {
        if (c + 1 < nchunk) { CP_ASYNC_WAIT(1); } else { CP_ASYNC_WAIT(0); }
        __syncthreads();

        const bool pf = (c + 2 < nchunk);
        int is = st + 2; if (is >= 3) is -= 3;
        const uint32_t psa = sbase + is * STAGE_B + cpoff;
        const uint32_t psb = psa + STAGE_F * 4;
        const float* pga = gA + (c + 2) * 32;
        const float* pgw = gW + (c + 2) * 32;

        const uint32_t abase = sbase + st * STAGE_B;
        const uint32_t bbase = abase + STAGE_F * 4;
#pragma unroll
        for (int s = 0; s < 4; s++) {
            uint32_t af[4][4], bp[2][4];
#pragma unroll
            for (int mt = 0; mt < 4; mt++)
                ldsm_x4(af[mt], abase + aoff[mt] + s * 32);
#pragma unroll
            for (int p = 0; p < 2; p++)
                ldsm_x4(bp[p], bbase + boff[p] + s * 32);
#pragma unroll
            for (int mt = 0; mt < 4; mt++)
#pragma unroll
                for (int nt = 0; nt < 4; nt++)
                    mma_tf32(acc[mt][nt], af[mt], &bp[nt >> 1][(nt & 1) * 2]);
            if (pf) {
                cp_async16(psa + s * 16, pga + s * 4);
                cp_async16(psb + s * 16, pgw + s * 4);
            }
        }
        if (pf) CP_ASYNC_COMMIT();
        st = (st + 1 == 3) ? 0 : st + 1;
    }

    const int relu = flags & 1;
    const int rnd  = flags & 2;
    const int r0  = bm * 128 + warp_m * 64;
    const int c0g = bn * 128 + warp_n * 32;

    if (vt != nullptr && bn * 128 >= vcol0) {
        // transposed V epilogue: vt[b, h, d, s]
        const int bb = (bm * 128) >> 11;         // batch of this tile (no crossing)
        float* vtb = vt + (size_t)bb * NHEAD * DHEAD * SEQ;
#pragma unroll
        for (int n = 0; n < 4; n++) {
            const int colr = c0g + n * 8 + 2 * lc - vcol0;
            const int hd0 = colr;                 // h*64 + d
            float2 bv = *(const float2*)(bias + c0g + n * 8 + 2 * lc);
#pragma unroll
            for (int m = 0; m < 4; m++) {
                const int s = (r0 + m * 16 + lr) & (SEQ - 1);
                float v00 = acc[m][n][0] + bv.x;
                float v01 = acc[m][n][1] + bv.y;
                float v10 = acc[m][n][2] + bv.x;
                float v11 = acc[m][n][3] + bv.y;
                if (rnd) {
                    v00 = to_tf32(v00); v01 = to_tf32(v01);
                    v10 = to_tf32(v10); v11 = to_tf32(v11);
                }
                float* p0 = vtb + (size_t)hd0 * SEQ + s;
                float* p1 = vtb + (size_t)(hd0 + 1) * SEQ + s;
                p0[0] = v00; p1[0] = v01;
                p0[8] = v10; p1[8] = v11;
            }
        }
        return;
    }

#pragma unroll
    for (int n = 0; n < 4; n++) {
        const int col = c0g + n * 8 + 2 * lc;
        float2 bv = *(const float2*)(bias + col);
#pragma unroll
        for (int m = 0; m < 4; m++) {
            const int r = r0 + m * 16 + lr;
            float2 v0 = make_float2(acc[m][n][0] + bv.x, acc[m][n][1] + bv.y);
            float2 v1 = make_float2(acc[m][n][2] + bv.x, acc[m][n][3] + bv.y);
            if (relu) {
                v0.x = fmaxf(v0.x, 0.f); v0.y = fmaxf(v0.y, 0.f);
                v1.x = fmaxf(v1.x, 0.f); v1.y = fmaxf(v1.y, 0.f);
            }
            if (rnd) {
                v0.x = to_tf32(v0.x); v0.y = to_tf32(v0.y);
                v1.x = to_tf32(v1.x); v1.y = to_tf32(v1.y);
            }
            *(float2*)(C + (size_t)r * N + col)       = v0;
            *(float2*)(C + (size_t)(r + 8) * N + col) = v1;
        }
    }
}

__global__ void __launch_bounds__(256, 2) gemm_tc(
    const float* __restrict__ A, const float* __restrict__ W,
    const float* __restrict__ bias, float* __restrict__ C,
    int M, int N, int K, int flags, float* vt, int vcol0)
{
    extern __shared__ float smem[];
    gemm_body(A, W, bias, C, N, K, flags, blockIdx.y, blockIdx.x, smem, vt, vcol0);
}

// Two independent GEMMs (same M, K, rounded output) in one launch; each side
// may route its V column range to a transposed-V buffer.
__global__ void __launch_bounds__(256, 2) gemm_tc_dual(
    const float* __restrict__ A1, const float* __restrict__ W1,
    const float* __restrict__ b1, float* __restrict__ C1, int N1,
    float* vt1, int vcol01,
    const float* __restrict__ A2, const float* __restrict__ W2,
    const float* __restrict__ b2, float* __restrict__ C2, int N2,
    float* vt2, int vcol02,
    int K)
{
    extern __shared__ float smem[];
    const int split = N1 >> 7;
    if ((int)blockIdx.x < split)
        gemm_body(A1, W1, b1, C1, N1, K, 2, blockIdx.y, blockIdx.x, smem,
                  vt1, vcol01);
    else
        gemm_body(A2, W2, b2, C2, N2, K, 2, blockIdx.y, blockIdx.x - split, smem,
                  vt2, vcol02);
}

// ============================================================================
// Tensor-core flash attention: 128x64 tiles, 8 warps, K/V depth-2 cp.async.
// K from kv-major buffer (S-phase ldmatrix B-frags); V from d-major vt buffer
// (PV-phase ldmatrix B-frags, same pattern). P A-frags via ldmatrix.
// ============================================================================
#define KP 68
#define VP 68
#define PP 76
#define ATTN_SMEM ((2*64*KP + 2*64*VP + 128*PP) * 4)   // 108544 bytes

__global__ void __launch_bounds__(256, 2) attn_tc(
    const float* __restrict__ Q, const float* __restrict__ K,
    const float* __restrict__ VT, const int* __restrict__ mask,
    float* __restrict__ O, int Skv, int causal, int qs, int ks)
{
    extern __shared__ float sm[];
    float* p_s = sm + 2 * 64 * KP + 2 * 64 * VP; // [128][PP]

    const int t    = threadIdx.x;
    const int lane = t & 31;
    const int wid  = t >> 5;
    const int lr   = lane >> 2;
    const int lc   = lane & 3;
    const int wr0  = wid * 16;
    const int qt   = causal ? (gridDim.x - 1 - blockIdx.x) : blockIdx.x;
    const int h    = blockIdx.y;
    const int b    = blockIdx.z;
    const int qrow0 = qt * 128;

    const size_t qbase  = ((size_t)(b * SEQ + qrow0)) * qs + h * DHEAD;
    const size_t obase  = ((size_t)(b * SEQ + qrow0)) * D_MODEL + h * DHEAD;
    const size_t vtbase = ((size_t)(b * NHEAD + h)) * DHEAD * Skv;
    const uint32_t smadr = (uint32_t)__cvta_generic_to_shared(sm);
    const uint32_t kadr  = smadr;
    const uint32_t vadr  = smadr + 2 * 64 * KP * 4;
    const uint32_t padr  = smadr + (2 * 64 * KP + 2 * 64 * VP) * 4;

    const int g8 = lane >> 3, r8 = lane & 7;
    uint32_t kboff[4], vboff[4];
#pragma unroll
    for (int p = 0; p < 4; p++) {
        int rr = p * 16 + (g8 >> 1) * 8 + r8;
        int cc = (g8 & 1) * 4;
        kboff[p] = (rr * KP + cc) * 4;
        vboff[p] = (rr * VP + cc) * 4;
    }
    const uint32_t paoff = ((wr0 + (g8 & 1) * 8 + r8) * PP + (g8 >> 1) * 4) * 4;

    const int ntiles = causal ? (2 * qt + 2) : (Skv >> 6);

    // ---- prologue: issue K/V tiles 0,1 ----
#pragma unroll
    for (int pt = 0; pt < 2; pt++) {
        if (pt < ntiles) {
            const size_t kb = ((size_t)(b * Skv + pt * 64)) * ks + h * DHEAD;
            const uint32_t ka = kadr + pt * 64 * KP * 4;
            const uint32_t va = vadr + pt * 64 * VP * 4;
#pragma unroll
            for (int e = 0; e < 4; e++) {
                int f4 = e * 256 + t;
                int r = f4 >> 4, c4 = f4 & 15;
                cp_async16(ka + (r * KP + c4 * 4) * 4,
                           K + kb + (size_t)r * ks + c4 * 4);
                cp_async16(va + (r * VP + c4 * 4) * 4,
                           VT + vtbase + (size_t)r * Skv + pt * 64 + c4 * 4);
            }
            CP_ASYNC_COMMIT();
        }
    }

    // ---- stage Q (scale by 1/8; pre-rounded tf32, scale exact) ----
#pragma unroll
    for (int e = 0; e < 8; e++) {
        int f4 = e * 256 + t;
        int r = f4 >> 4, c4 = f4 & 15;
        float4 qv = *(const float4*)(Q + qbase + (size_t)r * qs + c4 * 4);
        float* dst = p_s + r * PP + c4 * 4;
        dst[0] = qv.x * 0.125f;
        dst[1] = qv.y * 0.125f;
        dst[2] = qv.z * 0.125f;
        dst[3] = qv.w * 0.125f;
    }
    __syncthreads();
    uint32_t qa[8][4];
#pragma unroll
    for (int kf = 0; kf < 8; kf++)
        ldsm_x4(qa[kf], padr + paoff + kf * 32);

    float m_i[2] = {-1e30f, -1e30f};
    float l_i[2] = {0.f, 0.f};
    float oacc[8][4];
#pragma unroll
    for (int nf = 0; nf < 8; nf++)
#pragma unroll
        for (int e = 0; e < 4; e++) oacc[nf][e] = 0.f;

    const int r0g = qrow0 + wr0 + lr;

    for (int jt = 0; jt < ntiles; jt++) {
        if (jt + 1 < ntiles) { CP_ASYNC_WAIT(1); } else { CP_ASYNC_WAIT(0); }
        __syncthreads();

        const uint32_t kst = kadr + (jt & 1) * 64 * KP * 4;
        const uint32_t vst = vadr + (jt & 1) * 64 * VP * 4;

        // ---- S = Q K^T (ldmatrix B-frags) ----
        float sacc[8][4];
#pragma unroll
        for (int nf = 0; nf < 8; nf++)
#pragma unroll
            for (int e = 0; e < 4; e++) sacc[nf][e] = 0.f;

#pragma unroll
        for (int kk = 0; kk < 8; kk++) {
            uint32_t bp[4][4];
#pragma unroll
            for (int p = 0; p < 4; p++)
                ldsm_x4(bp[p], kst + kboff[p] + kk * 32);
#pragma unroll
            for (int nf = 0; nf < 8; nf++)
                mma_tf32(sacc[nf], qa[kk], &bp[nf >> 1][(nf & 1) * 2]);
        }

        if (causal) {
            if (jt >= 2 * qt) {
#pragma unroll
                for (int nf = 0; nf < 8; nf++) {
                    int c0 = jt * 64 + nf * 8 + 2 * lc;
                    if (c0     > r0g)     sacc[nf][0] = -1e9f;
                    if (c0 + 1 > r0g)     sacc[nf][1] = -1e9f;
                    if (c0     > r0g + 8) sacc[nf][2] = -1e9f;
                    if (c0 + 1 > r0g + 8) sacc[nf][3] = -1e9f;
                }
            }
        } else {
            const int* mrow0 = mask + ((size_t)b * SEQ + r0g) * Skv + jt * 64;
            const int* mrow1 = mrow0 + 8 * Skv;
#pragma unroll
            for (int nf = 0; nf < 8; nf++) {
                int2 m0 = *(const int2*)(mrow0 + nf * 8 + 2 * lc);
                int2 m1 = *(const int2*)(mrow1 + nf * 8 + 2 * lc);
                if (!m0.x) sacc[nf][0] = -1e9f;
                if (!m0.y) sacc[nf][1] = -1e9f;
                if (!m1.x) sacc[nf][2] = -1e9f;
                if (!m1.y) sacc[nf][3] = -1e9f;
            }
        }

        // ---- online softmax (raw-fp32 P store; HW truncates operand) ----
        float mx0 = -1e30f, mx1 = -1e30f;
#pragma unroll
        for (int nf = 0; nf < 8; nf++) {
            mx0 = fmaxf(mx0, fmaxf(sacc[nf][0], sacc[nf][1]));
            mx1 = fmaxf(mx1, fmaxf(sacc[nf][2], sacc[nf][3]));
        }
        mx0 = fmaxf(mx0, __shfl_xor_sync(0xffffffffu, mx0, 1));
        mx0 = fmaxf(mx0, __shfl_xor_sync(0xffffffffu, mx0, 2));
        mx1 = fmaxf(mx1, __shfl_xor_sync(0xffffffffu, mx1, 1));
        mx1 = fmaxf(mx1, __shfl_xor_sync(0xffffffffu, mx1, 2));
        float newm0 = fmaxf(m_i[0], mx0);
        float newm1 = fmaxf(m_i[1], mx1);
        float a0 = __expf(m_i[0] - newm0);
        float a1 = __expf(m_i[1] - newm1);
        m_i[0] = newm0; m_i[1] = newm1;

        float rs0 = 0.f, rs1 = 0.f;
#pragma unroll
        for (int nf = 0; nf < 8; nf++) {
            float p0 = __expf(sacc[nf][0] - newm0);
            float p1 = __expf(sacc[nf][1] - newm0);
            float p2 = __expf(sacc[nf][2] - newm1);
            float p3 = __expf(sacc[nf][3] - newm1);
            rs0 += p0 + p1;
            rs1 += p2 + p3;
            float* pr0 = p_s + (wr0 + lr) * PP + nf * 8 + 2 * lc;
            *(float2*)pr0            = make_float2(p0, p1);
            *(float2*)(pr0 + 8 * PP) = make_float2(p2, p3);
            oacc[nf][0] *= a0; oacc[nf][1] *= a0;
            oacc[nf][2] *= a1; oacc[nf][3] *= a1;
        }
        rs0 += __shfl_xor_sync(0xffffffffu, rs0, 1);
        rs0 += __shfl_xor_sync(0xffffffffu, rs0, 2);
        rs1 += __shfl_xor_sync(0xffffffffu, rs1, 1);
        rs1 += __shfl_xor_sync(0xffffffffu, rs1, 2);
        l_i[0] = l_i[0] * a0 + rs0;
        l_i[1] = l_i[1] * a1 + rs1;
        __syncwarp();   // p_s rows are warp-private

        // ---- O += P V (ldmatrix P A-frags + ldmatrix V^T B-frags) ----
#pragma unroll
        for (int kk = 0; kk < 8; kk++) {
            uint32_t af[4];
            ldsm_x4(af, padr + paoff + kk * 32);
            uint32_t bp[4][4];
#pragma unroll
            for (int p = 0; p < 4; p++)
                ldsm_x4(bp[p], vst + vboff[p] + kk * 32);
#pragma unroll
            for (int nf = 0; nf < 8; nf++)
                mma_tf32(oacc[nf], af, &bp[nf >> 1][(nf & 1) * 2]);
        }

        __syncthreads();   // all warps done reading stage (jt&1) before refill
        if (jt + 2 < ntiles) {
            const int s = jt & 1;
            const size_t kb = ((size_t)(b * Skv + (jt + 2) * 64)) * ks + h * DHEAD;
            const uint32_t ka = kadr + s * 64 * KP * 4;
            const uint32_t va = vadr + s * 64 * VP * 4;
#pragma unroll
            for (int e = 0; e < 4; e++) {
                int f4 = e * 256 + t;
                int r = f4 >> 4, c4 = f4 & 15;
                cp_async16(ka + (r * KP + c4 * 4) * 4,
                           K + kb + (size_t)r * ks + c4 * 4);
                cp_async16(va + (r * VP + c4 * 4) * 4,
                           VT + vtbase + (size_t)r * Skv + (jt + 2) * 64 + c4 * 4);
            }
            CP_ASYNC_COMMIT();
        }
    }

    // store tf32-rounded ctx (feeds O-projection GEMM)
    float inv0 = 1.f / l_i[0];
    float inv1 = 1.f / l_i[1];
#pragma unroll
    for (int nf = 0; nf < 8; nf++) {
        float* o0 = O + obase + (size_t)(wr0 + lr) * D_MODEL + nf * 8 + 2 * lc;
        float* o1 = o0 + 8 * D_MODEL;
        *(float2*)o0 = make_float2(to_tf32(oacc[nf][0] * inv0),
                                   to_tf32(oacc[nf][1] * inv0));
        *(float2*)o1 = make_float2(to_tf32(oacc[nf][2] * inv1),
                                   to_tf32(oacc[nf][3] * inv1));
    }
}

// ---------------- fused residual add + LayerNorm: warp-per-row --------------
__global__ void __launch_bounds__(256) add_ln_kernel(
    const float* __restrict__ a, const float* __restrict__ r,
    const float* __restrict__ g, const float* __restrict__ be,
    float* __restrict__ out, float* __restrict__ out_t)
{
    const int row  = (blockIdx.x * blockDim.x + threadIdx.x) >> 5;
    const int lane = threadIdx.x & 31;
    const size_t base = (size_t)row * D_MODEL;

    float v[32];
    float s = 0.f, q = 0.f;
#pragma unroll
    for (int i = 0; i < 8; i++) {
        const int col = lane * 4 + i * 128;
        float4 va = *(const float4*)(a + base + col);
        float4 vr = *(const float4*)(r + base + col);
        float v0 = va.x + vr.x, v1 = va.y + vr.y;
        float v2 = va.z + vr.z, v3 = va.w + vr.w;
        v[i * 4 + 0] = v0; v[i * 4 + 1] = v1; v[i * 4 + 2] = v2; v[i * 4 + 3] = v3;
        s += v0 + v1 + v2 + v3;
        q += v0 * v0 + v1 * v1 + v2 * v2 + v3 * v3;
    }
#pragma unroll
    for (int off = 16; off >= 1; off >>= 1) {
        s += __shfl_xor_sync(0xffffffffu, s, off);
        q += __shfl_xor_sync(0xffffffffu, q, off);
    }
    float mu  = s * (1.f / D_MODEL);
    float var = q * (1.f / D_MODEL) - mu * mu;
    float rstd = rsqrtf(var + 1e-5f);

#pragma unroll
    for (int i = 0; i < 8; i++) {
        const int col = lane * 4 + i * 128;
        float4 vg = *(const float4*)(g + col);
        float4 vb = *(const float4*)(be + col);
        float4 o;
        o.x = (v[i * 4 + 0] - mu) * rstd * vg.x + vb.x;
        o.y = (v[i * 4 + 1] - mu) * rstd * vg.y + vb.y;
        o.z = (v[i * 4 + 2] - mu) * rstd * vg.z + vb.z;
        o.w = (v[i * 4 + 3] - mu) * rstd * vg.w + vb.w;
        *(float4*)(out + base + col) = o;
        if (out_t)
            *(float4*)(out_t + base + col) =
                make_float4(to_tf32(o.x), to_tf32(o.y), to_tf32(o.z), to_tf32(o.w));
    }
}

// ---------------- launch ----------------------------------------------------
static void run_gemm(const float* A, const float* W, const float* b, float* C,
                     int M, int N, int K, int flags,
                     float* vt = nullptr, int vcol0 = 0)
{
    dim3 grid(N / 128, M / 128);
    gemm_tc<<<grid, 256, GEMM_SMEM>>>(A, W, b, C, M, N, K, flags, vt, vcol0);
}

extern "C" void kernel_launch(void* const* d_in, const int* in_sizes, int n_in,
                              void* d_out, int out_size)
{
    (void)in_sizes; (void)n_in; (void)out_size;
    const float* x    = (const float*)d_in[0];
    const float* enc  = (const float*)d_in[1];
    const int* src_mask = (const int*)d_in[2];
    const int* tgt_mask = (const int*)d_in[3];
    const float* sa_Wq = (const float*)d_in[4];
    const float* sa_bq = (const float*)d_in[5];
    const float* sa_Wk = (const float*)d_in[6];
    const float* sa_bk = (const float*)d_in[7];
    const float* sa_Wv = (const float*)d_in[8];
    const float* sa_bv = (const float*)d_in[9];
    const float* sa_Wo = (const float*)d_in[10];
    const float* sa_bo = (const float*)d_in[11];
    const float* ca_Wq = (const float*)d_in[12];
    const float* ca_bq = (const float*)d_in[13];
    const float* ca_Wk = (const float*)d_in[14];
    const float* ca_bk = (const float*)d_in[15];
    const float* ca_Wv = (const float*)d_in[16];
    const float* ca_bv = (const float*)d_in[17];
    const float* ca_Wo = (const float*)d_in[18];
    const float* ca_bo = (const float*)d_in[19];
    const float* ff_W1 = (const float*)d_in[20];
    const float* ff_b1 = (const float*)d_in[21];
    const float* ff_W2 = (const float*)d_in[22];
    const float* ff_b2 = (const float*)d_in[23];
    const float* ln1_g = (const float*)d_in[24];
    const float* ln1_b = (const float*)d_in[25];
    const float* ln2_g = (const float*)d_in[26];
    const float* ln2_b = (const float*)d_in[27];
    const float* ln3_g = (const float*)d_in[28];
    const float* ln3_b = (const float*)d_in[29];
    float* out = (float*)d_out;

    float *q, *ctx, *tmp, *x1, *x2, *ff;
    float *wc, *xq, *enct, *x1t, *x2t, *qkv, *kv, *vtA, *vtB, *bqkv, *bkv;
    cudaGetSymbolAddress((void**)&q,    g_q);
    cudaGetSymbolAddress((void**)&ctx,  g_ctx);
    cudaGetSymbolAddress((void**)&tmp,  g_tmp);
    cudaGetSymbolAddress((void**)&x1,   g_x1);
    cudaGetSymbolAddress((void**)&x2,   g_x2);
    cudaGetSymbolAddress((void**)&ff,   g_ff);
    cudaGetSymbolAddress((void**)&wc,   g_wc);
    cudaGetSymbolAddress((void**)&xq,   g_xq);
    cudaGetSymbolAddress((void**)&enct, g_enct);
    cudaGetSymbolAddress((void**)&x1t,  g_x1t);
    cudaGetSymbolAddress((void**)&x2t,  g_x2t);
    cudaGetSymbolAddress((void**)&qkv,  g_qkv);
    cudaGetSymbolAddress((void**)&kv,   g_kv);
    cudaGetSymbolAddress((void**)&vtA,  g_vtA);
    cudaGetSymbolAddress((void**)&vtB,  g_vtB);
    cudaGetSymbolAddress((void**)&bqkv, g_bqkv);
    cudaGetSymbolAddress((void**)&bkv,  g_bkv);

    cudaFuncSetAttribute(gemm_tc, cudaFuncAttributeMaxDynamicSharedMemorySize,
                         GEMM_SMEM);
    cudaFuncSetAttribute(gemm_tc_dual, cudaFuncAttributeMaxDynamicSharedMemorySize,
                         GEMM_SMEM);
    cudaFuncSetAttribute(attn_tc, cudaFuncAttributeMaxDynamicSharedMemorySize,
                         ATTN_SMEM);

    float* wSAQ = wc + 0 * MB;  // wSAK, wSAV contiguous after -> fused QKV W
    float* wSAO = wc + 3 * MB;
    float* wCAQ = wc + 4 * MB;
    float* wCAK = wc + 5 * MB;  // wCAV contiguous after -> fused KV W
    float* wCAO = wc + 7 * MB;
    float* wFF1 = wc + 8 * MB;  float* wFF2 = wc + 12 * MB;

    CvtJobs jobs;
    const float* srcs[NJOBS] = {sa_Wq, sa_Wk, sa_Wv, sa_Wo, ca_Wq, ca_Wk, ca_Wv,
                                ca_Wo, ff_W1, ff_W2, x, enc,
                                sa_bq, sa_bk, sa_bv, ca_bk, ca_bv};
    float* dsts[NJOBS] = {wc, wc + MB, wc + 2 * MB, wSAO, wCAQ, wCAK, wc + 6 * MB,
                          wCAO, wFF1, wFF2, xq, enct,
                          bqkv, bqkv + D_MODEL, bqkv + 2 * D_MODEL,
                          bkv, bkv + D_MODEL};
    int n4s[NJOBS] = {MB/4, MB/4, MB/4, MB/4, MB/4, MB/4, MB/4, MB/4,
                      MB, MB, MB, MB, 256, 256, 256, 256, 256};
    int rnds[NJOBS] = {1,1,1,1,1,1,1,1,1,1,1,1, 0,0,0,0,0};
    for (int i = 0; i < NJOBS; i++) {
        jobs.src[i] = srcs[i]; jobs.dst[i] = dsts[i];
        jobs.n4[i] = n4s[i];   jobs.rnd[i] = rnds[i];
    }
    cvt_batch_kernel<<<dim3(1024, NJOBS), 256>>>(jobs);

    dim3 agrid(SEQ / 128, NHEAD, BATCH);
    const int LN_BLOCKS = MROWS / 8;

    // ---- mega projection launch: self QKV (N=3072) + cross KV (N=2048) ----
    // Both depend only on cvt outputs; packing them into one launch removes a
    // boundary and fills ragged tails. V columns route to vtA / vtB.
    {
        dim3 grid((3 * D_MODEL + 2 * D_MODEL) / 128, MROWS / 128);
        gemm_tc_dual<<<grid, 256, GEMM_SMEM>>>(
            xq,   wSAQ, bqkv, qkv, 3 * D_MODEL, vtA, 2 * D_MODEL,
            enct, wCAK, bkv,  kv,  2 * D_MODEL, vtB, D_MODEL,
            D_MODEL);
    }

    // ---- self-attention ----
    attn_tc<<<agrid, 256, ATTN_SMEM>>>(qkv, qkv + D_MODEL, vtA,
                                       tgt_mask, ctx, SEQ, 1,
                                       3 * D_MODEL, 3 * D_MODEL);
    run_gemm(ctx, wSAO, sa_bo, tmp, MROWS, D_MODEL, D_MODEL, 0);
    add_ln_kernel<<<LN_BLOCKS, 256>>>(x, tmp, ln1_g, ln1_b, x1, x1t);

    // ---- cross-attention (KV already computed) ----
    run_gemm(x1t, wCAQ, ca_bq, q, MROWS, D_MODEL, D_MODEL, 2);
    attn_tc<<<agrid, 256, ATTN_SMEM>>>(q, kv, vtB,
                                       src_mask, ctx, SEQ, 0,
                                       D_MODEL, 2 * D_MODEL);
    run_gemm(ctx, wCAO, ca_bo, tmp, MROWS, D_MODEL, D_MODEL, 0);
    add_ln_kernel<<<LN_BLOCKS, 256>>>(x1, tmp, ln2_g, ln2_b, x2, x2t);

    // ---- feed-forward ----
    run_gemm(x2t, wFF1, ff_b1, ff, MROWS, DFF_SZ, D_MODEL, 1 | 2);
    run_gemm(ff,  wFF2, ff_b2, tmp, MROWS, D_MODEL, DFF_SZ, 0);
    add_ln_kernel<<<LN_BLOCKS, 256>>>(x2, tmp, ln3_g, ln3_b, out, nullptr);
}